// round 3
// baseline (speedup 1.0000x reference)
#include <cuda_runtime.h>
#include <math.h>

#define N_TOK 4096
#define D_DIM 2048
#define N_EXP 8
#define TOPK  2
#define CAP   512
#define PITCH 1028          // padded smem row (floats)
#define TPW   4             // tokens per warp
#define BLK   256
#define GRID1 (N_TOK / (8 * TPW))   // 128 blocks, 1 wave, 1 block/SM

__device__ int g_choice[N_TOK * TOPK];

// ---------------------------------------------------------------------------
// Kernel 1: logits GEMM + top-2 + softmax, with dispatcher ZEROING fused into
// the mainloop (write stream overlaps the x read stream via MLP).
// W staged transposed in smem (conflict-free float4 LDS). 4 tokens/warp.
// ---------------------------------------------------------------------------
__global__ __launch_bounds__(BLK) void k_logits_zero(
        const float* __restrict__ x,
        const float* __restrict__ W,
        float* __restrict__ out) {
    __shared__ float wt[N_EXP * PITCH];   // 8 x 1028 floats = 32.9 KB (one 1024-d phase)

    int tid  = threadIdx.x;
    int lane = tid & 31;
    int wrp  = tid >> 5;
    int t0   = (blockIdx.x * 8 + wrp) * TPW;

    const float4* x4 = reinterpret_cast<const float4*>(x);
    float4* z4 = reinterpret_cast<float4*>(out);
    size_t zbase = (size_t)blockIdx.x * 32768;   // 4.19M float4 / 128 blocks

    float acc[TPW][N_EXP] = {};

    for (int p = 0; p < 2; p++) {
        // cooperative transposed stage of W[p*1024 .. +1024)
        for (int idx = tid; idx < 1024 * N_EXP; idx += BLK) {
            int dl = idx >> 3;
            int e  = idx & 7;
            wt[e * PITCH + dl] = W[(p * 1024 + dl) * N_EXP + e];
        }
        __syncthreads();

        #pragma unroll
        for (int i = 0; i < 8; i++) {
            int j = i * 32 + lane;   // float4 index within phase [0,256)
            float4 xv[TPW];
            #pragma unroll
            for (int t = 0; t < TPW; t++)
                xv[t] = __ldg(&x4[(size_t)(t0 + t) * (D_DIM / 4) + p * 256 + j]);

            // interleaved zero chunk: 8 float4 per thread per step,
            // lane-contiguous addressing (4 lines per STG.128)
            int step = p * 8 + i;
            #pragma unroll
            for (int q = 0; q < 8; q++)
                z4[zbase + (size_t)step * 2048 + q * 256 + tid] =
                    make_float4(0.f, 0.f, 0.f, 0.f);

            #pragma unroll
            for (int e = 0; e < N_EXP; e++) {
                float4 w = *reinterpret_cast<const float4*>(&wt[e * PITCH + j * 4]);
                #pragma unroll
                for (int t = 0; t < TPW; t++)
                    acc[t][e] += xv[t].x * w.x + xv[t].y * w.y +
                                 xv[t].z * w.z + xv[t].w * w.w;
            }
        }
        __syncthreads();
    }

    // warp-reduce all TPW*8 logits (xor butterfly)
    #pragma unroll
    for (int t = 0; t < TPW; t++)
        #pragma unroll
        for (int e = 0; e < N_EXP; e++)
            #pragma unroll
            for (int off = 16; off > 0; off >>= 1)
                acc[t][e] += __shfl_xor_sync(0xffffffffu, acc[t][e], off);

    if (lane == 0) {
        float* gate = out + (size_t)N_TOK * N_EXP * CAP;
        float* idxf = gate + N_TOK * TOPK;
        #pragma unroll
        for (int t = 0; t < TPW; t++) {
            int tok = t0 + t;
            float best = -INFINITY, sec = -INFINITY;
            int bi = 0, si = 0;
            #pragma unroll
            for (int e = 0; e < N_EXP; e++) {
                float v = acc[t][e];
                if (v > best)     { sec = best; si = bi; best = v; bi = e; }
                else if (v > sec) { sec = v;    si = e; }
            }
            float g0 = 1.0f / (1.0f + expf(sec - best));
            gate[tok * 2 + 0] = g0;
            gate[tok * 2 + 1] = 1.0f - g0;
            idxf[tok * 2 + 0] = (float)bi;
            idxf[tok * 2 + 1] = (float)si;
            g_choice[tok * 2 + 0] = bi;
            g_choice[tok * 2 + 1] = si;
        }
    }
}

// ---------------------------------------------------------------------------
// Kernel 2: per-(k,expert) prefix scan over 4096 tokens, fused with scatter:
// writes the 1.0f dispatcher entries directly (zeros already laid by k1).
// 16 blocks (one per (k,e)), 1024 threads, 4 tokens/thread.
// ---------------------------------------------------------------------------
__global__ void k_scan_scatter(float* __restrict__ out) {
    int k = blockIdx.x >> 3;
    int e = blockIdx.x & 7;
    int tid  = threadIdx.x;
    int lane = tid & 31;
    int wid  = tid >> 5;

    __shared__ int warp_sums[32];

    int n0 = tid * 4;
    int flags[4];
    int localex[4];
    int s = 0;
    #pragma unroll
    for (int j = 0; j < 4; j++) {
        flags[j]   = (g_choice[(n0 + j) * 2 + k] == e) ? 1 : 0;
        localex[j] = s;
        s += flags[j];
    }

    int inc = s;
    #pragma unroll
    for (int off = 1; off < 32; off <<= 1) {
        int v = __shfl_up_sync(0xffffffffu, inc, off);
        if (lane >= off) inc += v;
    }
    if (lane == 31) warp_sums[wid] = inc;
    __syncthreads();

    if (wid == 0) {
        int v = warp_sums[lane];
        int winc = v;
        #pragma unroll
        for (int off = 1; off < 32; off <<= 1) {
            int u = __shfl_up_sync(0xffffffffu, winc, off);
            if (lane >= off) winc += u;
        }
        warp_sums[lane] = winc - v;
    }
    __syncthreads();

    int thread_prefix = warp_sums[wid] + (inc - s);

    #pragma unroll
    for (int j = 0; j < 4; j++) {
        if (flags[j]) {
            int pri = thread_prefix + localex[j] + 1;   // 1-based priority
            if (pri <= CAP)
                out[(size_t)(n0 + j) * (N_EXP * CAP) + e * CAP + (pri - 1)] = 1.0f;
        }
    }
}

// ---------------------------------------------------------------------------
extern "C" void kernel_launch(void* const* d_in, const int* in_sizes, int n_in,
                              void* d_out, int out_size) {
    const float* x = (const float*)d_in[0];   // [4096, 2048]
    const float* W = (const float*)d_in[1];   // [2048, 8]
    float* out = (float*)d_out;

    k_logits_zero<<<GRID1, BLK>>>(x, W, out);
    k_scan_scatter<<<16, 1024>>>(out);
}

// round 4
// speedup vs baseline: 1.1414x; 1.1414x over previous
#include <cuda_runtime.h>
#include <math.h>

#define N_TOK 4096
#define D_DIM 2048
#define N_EXP 8
#define TOPK  2
#define CAP   512
#define PITCH 2052                 // padded smem row (floats): bank-conflict-free
#define TPW   4                    // tokens per warp (GEMM path)
#define BLK   256
#define GEMM_BLOCKS 128            // 128 blk * 8 warps * 4 tok = 4096
#define FILL_BLOCKS 512            // 64MB / 512 = 128KB per block
#define DISP_F4 (N_TOK * N_EXP * CAP / 4)   // 4,194,304 float4

__device__ int g_choice[N_TOK * TOPK];

// ---------------------------------------------------------------------------
// Kernel A: block-specialized.
//   bid < 128 : logits GEMM + top-2 + softmax (W staged transposed in smem)
//   bid >= 128: zero-fill a chunk of the dispatcher (pure write stream)
// The two block families run concurrently across SMs, overlapping the x-read
// stream with the dispatcher-write stream without sharing instruction streams.
// ---------------------------------------------------------------------------
__global__ __launch_bounds__(BLK) void k_main(
        const float* __restrict__ x,
        const float* __restrict__ W,
        float* __restrict__ out) {
    __shared__ float wt[N_EXP * PITCH];   // 65.7 KB

    int tid = threadIdx.x;

    if (blockIdx.x >= GEMM_BLOCKS) {
        // ----------------- fill path: 8192 float4 per block -----------------
        float4* z4 = reinterpret_cast<float4*>(out);
        size_t base = (size_t)(blockIdx.x - GEMM_BLOCKS) * 8192;
        const float4 zero = make_float4(0.f, 0.f, 0.f, 0.f);
        #pragma unroll
        for (int q = 0; q < 32; q++)
            z4[base + q * 256 + tid] = zero;
        return;
    }

    // ------------------------- GEMM path --------------------------------
    int lane = tid & 31;
    int wrp  = tid >> 5;
    int t0   = (blockIdx.x * 8 + wrp) * TPW;

    // stage all of W transposed: wt[e][d]  (store pattern is conflict-free:
    // bank = (4e + d) % 32 distinct within each warp)
    for (int idx = tid; idx < D_DIM * N_EXP; idx += BLK) {
        int d = idx >> 3;
        int e = idx & 7;
        wt[e * PITCH + d] = W[idx];
    }
    __syncthreads();

    const float4* x4 = reinterpret_cast<const float4*>(x);
    float acc[TPW][N_EXP] = {};

    #pragma unroll 4
    for (int i = 0; i < 16; i++) {
        int j = i * 32 + lane;                 // float4 index in [0,512)
        float4 xv[TPW];
        #pragma unroll
        for (int t = 0; t < TPW; t++)
            xv[t] = __ldg(&x4[(size_t)(t0 + t) * (D_DIM / 4) + j]);
        #pragma unroll
        for (int e = 0; e < N_EXP; e++) {
            float4 w = *reinterpret_cast<const float4*>(&wt[e * PITCH + j * 4]);
            #pragma unroll
            for (int t = 0; t < TPW; t++)
                acc[t][e] += xv[t].x * w.x + xv[t].y * w.y +
                             xv[t].z * w.z + xv[t].w * w.w;
        }
    }

    // warp-reduce all TPW*8 logits
    #pragma unroll
    for (int t = 0; t < TPW; t++)
        #pragma unroll
        for (int e = 0; e < N_EXP; e++)
            #pragma unroll
            for (int off = 16; off > 0; off >>= 1)
                acc[t][e] += __shfl_xor_sync(0xffffffffu, acc[t][e], off);

    if (lane == 0) {
        float* gate = out + (size_t)N_TOK * N_EXP * CAP;
        float* idxf = gate + N_TOK * TOPK;
        #pragma unroll
        for (int t = 0; t < TPW; t++) {
            int tok = t0 + t;
            float best = -INFINITY, sec = -INFINITY;
            int bi = 0, si = 0;
            #pragma unroll
            for (int e = 0; e < N_EXP; e++) {
                float v = acc[t][e];
                if (v > best)     { sec = best; si = bi; best = v; bi = e; }
                else if (v > sec) { sec = v;    si = e; }
            }
            float g0 = 1.0f / (1.0f + expf(sec - best));
            gate[tok * 2 + 0] = g0;
            gate[tok * 2 + 1] = 1.0f - g0;
            idxf[tok * 2 + 0] = (float)bi;
            idxf[tok * 2 + 1] = (float)si;
            g_choice[tok * 2 + 0] = bi;
            g_choice[tok * 2 + 1] = si;
        }
    }
}

// ---------------------------------------------------------------------------
// Kernel B: per-(k,expert) prefix scan over 4096 tokens + scatter of 1.0f
// (zeros already laid down by kernel A's fill blocks).
// 16 blocks (one per (k,e)), 1024 threads, 4 tokens/thread.
// ---------------------------------------------------------------------------
__global__ void k_scan_scatter(float* __restrict__ out) {
    int k = blockIdx.x >> 3;
    int e = blockIdx.x & 7;
    int tid  = threadIdx.x;
    int lane = tid & 31;
    int wid  = tid >> 5;

    __shared__ int warp_sums[32];

    int n0 = tid * 4;
    int flags[4];
    int localex[4];
    int s = 0;
    #pragma unroll
    for (int j = 0; j < 4; j++) {
        flags[j]   = (g_choice[(n0 + j) * 2 + k] == e) ? 1 : 0;
        localex[j] = s;
        s += flags[j];
    }

    int inc = s;
    #pragma unroll
    for (int off = 1; off < 32; off <<= 1) {
        int v = __shfl_up_sync(0xffffffffu, inc, off);
        if (lane >= off) inc += v;
    }
    if (lane == 31) warp_sums[wid] = inc;
    __syncthreads();

    if (wid == 0) {
        int v = warp_sums[lane];
        int winc = v;
        #pragma unroll
        for (int off = 1; off < 32; off <<= 1) {
            int u = __shfl_up_sync(0xffffffffu, winc, off);
            if (lane >= off) winc += u;
        }
        warp_sums[lane] = winc - v;
    }
    __syncthreads();

    int thread_prefix = warp_sums[wid] + (inc - s);

    #pragma unroll
    for (int j = 0; j < 4; j++) {
        if (flags[j]) {
            int pri = thread_prefix + localex[j] + 1;
            if (pri <= CAP)
                out[(size_t)(n0 + j) * (N_EXP * CAP) + e * CAP + (pri - 1)] = 1.0f;
        }
    }
}

// ---------------------------------------------------------------------------
extern "C" void kernel_launch(void* const* d_in, const int* in_sizes, int n_in,
                              void* d_out, int out_size) {
    const float* x = (const float*)d_in[0];   // [4096, 2048]
    const float* W = (const float*)d_in[1];   // [2048, 8]
    float* out = (float*)d_out;

    k_main<<<GEMM_BLOCKS + FILL_BLOCKS, BLK>>>(x, W, out);
    k_scan_scatter<<<16, 1024>>>(out);
}